// round 2
// baseline (speedup 1.0000x reference)
#include <cuda_runtime.h>
#include <cuda_bf16.h>
#include <cstdint>

#define BATCH 8

// ---------------- scratch (device globals; no allocations allowed) ----------------
#define MAXACT (8u*64u*128u*128u)
__device__ float g_bufA[MAXACT];
__device__ float g_bufB[MAXACT];
__device__ float g_col[75497472u];           // largest col: conv1_2 N=131072, K=576
__device__ float g_part[4u*512u*512u];       // split-K partials (layer 5)
__device__ int4   g_tabI[196416];
__device__ float4 g_tabW[196416];
__device__ float g_vec1[8*4096];
__device__ float g_vec2[8*4096];

#define TB128 0
#define TB64  147456
#define TB32  184320
#define TB16  193536
#define TB8   195840

#define FMA2(d, a, b) asm("fma.rn.f32x2 %0, %1, %2, %0;" : "+l"(d) : "l"(a), "l"(b))

// ---------------- offset table construction ----------------
__global__ void build_tab(int H, int base) {
    int t = blockIdx.x * blockDim.x + threadIdx.x;
    int HW = H * H;
    if (t >= HW * 9) return;
    int k = t % 9, pos = t / 9;
    int y = pos / H, x = pos % H;

    float cc = 0.5f * (float)H - 0.5f;
    float th = atan2f((float)x - cc, (float)y - cc);
    if (th < 0.f) th += 6.28318530717958647692f;
    th = rintf(th * 10000.0f) / 10000.0f;

    int ky = k / 3, kx = k % 3;
    float offy = 0.f, offx = 0.f;
    if (k != 4) {
        int m = (k < 4) ? k : k - 1;
        float ang = th + (float)(3.14159265358979323846 * 0.25 * (double)m);
        offy = cosf(ang) + (float)(1 - ky);
        offx = sinf(ang) + (float)(1 - kx);
    }
    float py = (float)(y - 1 + ky) + offy;
    float px = (float)(x - 1 + kx) + offx;
    float y0 = floorf(py), x0 = floorf(px);
    float fy = py - y0, fx = px - x0;
    float Hm = (float)(H - 1);

    float ys[2] = {y0, y0 + 1.f};
    float xs[2] = {x0, x0 + 1.f};
    float wy[2] = {1.f - fy, fy};
    float wx[2] = {1.f - fx, fx};

    int   ids[4];
    float ws[4];
    int q = 0;
    #pragma unroll
    for (int iy = 0; iy < 2; iy++) {
        #pragma unroll
        for (int ix = 0; ix < 2; ix++) {
            float yf = ys[iy], xf = xs[ix];
            bool v = (yf >= 0.f) && (yf <= Hm) && (xf >= 0.f) && (xf <= Hm);
            int yi = (int)fminf(fmaxf(yf, 0.f), Hm);
            int xi = (int)fminf(fmaxf(xf, 0.f), Hm);
            ids[q] = yi * H + xi;
            ws[q]  = v ? (wy[iy] * wx[ix]) : 0.f;
            q++;
        }
    }
    g_tabI[base + t] = make_int4(ids[0], ids[1], ids[2], ids[3]);
    g_tabW[base + t] = make_float4(ws[0], ws[1], ws[2], ws[3]);
}

// ---------------- deformable im2col: col[(c*9+k)*N + n] ----------------
__global__ void im2col_deform(const float* __restrict__ x, float* __restrict__ col,
                              int Cin, int HW, int N, int tabBase) {
    int n = blockIdx.x * blockDim.x + threadIdx.x;
    int k = blockIdx.y;
    if (n >= N) return;
    int pos = n % HW;
    int b   = n / HW;
    int4   id = g_tabI[tabBase + pos * 9 + k];
    float4 w  = g_tabW[tabBase + pos * 9 + k];
    const float* xb = x + (size_t)b * Cin * HW;
    float* cp = col + (size_t)k * N + n;
    size_t cstride = (size_t)9 * N;
    for (int c = 0; c < Cin; c++) {
        const float* xc = xb + (size_t)c * HW;
        float v = xc[id.x] * w.x + xc[id.y] * w.y + xc[id.z] * w.z + xc[id.w] * w.w;
        cp[(size_t)c * cstride] = v;
    }
}

// ---------------- packed-f32x2 SGEMM, 128x64 tile, fused ReLU / split-K ----------------
// A: col, K x N (row stride N). Wt: O x K row-major.
// gridDim.z==1: out = activations [b][o][pos], ReLU applied.
// gridDim.z>1:  out = partial slabs [z][o][n], no ReLU.
__global__ __launch_bounds__(256)
void gemm_f32x2(const float* __restrict__ A, const float* __restrict__ Wt,
                float* __restrict__ out, int N, int K, int chunk,
                int Cout, int HW) {
    __shared__ __align__(16) float As[16][128];   // natural K x N tile
    __shared__ __align__(16) float Bs[16][128];   // duplicated: Bs[k][2*o] = Bs[k][2*o+1] = W

    int tid = threadIdx.x;
    int bn = blockIdx.x * 128;
    int bo = blockIdx.y * 64;
    int kStart = blockIdx.z * chunk;
    int kEnd = min(K, kStart + chunk);
    int tx = tid & 15;          // o groups of 4
    int ty = tid >> 4;          // n groups of 8

    int la_k = tid >> 4;
    int la_n = (tid & 15) * 8;
    int lb_o = tid & 63;
    int lb_k = (tid >> 6) * 4;
    const float* wrow = Wt + (size_t)(bo + lb_o) * K;

    unsigned long long acc[4][4];
    #pragma unroll
    for (int i = 0; i < 4; i++)
        #pragma unroll
        for (int j = 0; j < 4; j++) acc[i][j] = 0ull;

    float4 pa0, pa1;
    float pb[4];
    const float4 fz = make_float4(0.f, 0.f, 0.f, 0.f);

    // prefetch first k-block
    {
        int ka = kStart + la_k;
        if (ka < kEnd) {
            pa0 = *(const float4*)&A[(size_t)ka * N + bn + la_n];
            pa1 = *(const float4*)&A[(size_t)ka * N + bn + la_n + 4];
        } else { pa0 = fz; pa1 = fz; }
        #pragma unroll
        for (int j = 0; j < 4; j++) {
            int kb = kStart + lb_k + j;
            pb[j] = (kb < kEnd) ? wrow[kb] : 0.f;
        }
    }
    *(float4*)&As[la_k][la_n] = pa0;
    *(float4*)&As[la_k][la_n + 4] = pa1;
    #pragma unroll
    for (int j = 0; j < 4; j++)
        *(float2*)&Bs[lb_k + j][2 * lb_o] = make_float2(pb[j], pb[j]);
    __syncthreads();

    int nk = (kEnd - kStart + 15) >> 4;
    for (int it = 1; it < nk; it++) {
        int k0 = kStart + it * 16;
        // prefetch next
        int ka = k0 + la_k;
        if (ka < kEnd) {
            pa0 = *(const float4*)&A[(size_t)ka * N + bn + la_n];
            pa1 = *(const float4*)&A[(size_t)ka * N + bn + la_n + 4];
        } else { pa0 = fz; pa1 = fz; }
        #pragma unroll
        for (int j = 0; j < 4; j++) {
            int kb = k0 + lb_k + j;
            pb[j] = (kb < kEnd) ? wrow[kb] : 0.f;
        }
        // compute current
        #pragma unroll
        for (int kk = 0; kk < 16; kk++) {
            ulonglong2 aA = *(const ulonglong2*)&As[kk][ty * 8];
            ulonglong2 aB = *(const ulonglong2*)&As[kk][ty * 8 + 4];
            ulonglong2 bA = *(const ulonglong2*)&Bs[kk][tx * 8];
            ulonglong2 bB = *(const ulonglong2*)&Bs[kk][tx * 8 + 4];
            FMA2(acc[0][0], aA.x, bA.x); FMA2(acc[0][1], aA.x, bA.y);
            FMA2(acc[0][2], aA.x, bB.x); FMA2(acc[0][3], aA.x, bB.y);
            FMA2(acc[1][0], aA.y, bA.x); FMA2(acc[1][1], aA.y, bA.y);
            FMA2(acc[1][2], aA.y, bB.x); FMA2(acc[1][3], aA.y, bB.y);
            FMA2(acc[2][0], aB.x, bA.x); FMA2(acc[2][1], aB.x, bA.y);
            FMA2(acc[2][2], aB.x, bB.x); FMA2(acc[2][3], aB.x, bB.y);
            FMA2(acc[3][0], aB.y, bA.x); FMA2(acc[3][1], aB.y, bA.y);
            FMA2(acc[3][2], aB.y, bB.x); FMA2(acc[3][3], aB.y, bB.y);
        }
        __syncthreads();
        *(float4*)&As[la_k][la_n] = pa0;
        *(float4*)&As[la_k][la_n + 4] = pa1;
        #pragma unroll
        for (int j = 0; j < 4; j++)
            *(float2*)&Bs[lb_k + j][2 * lb_o] = make_float2(pb[j], pb[j]);
        __syncthreads();
    }
    // last k-block
    #pragma unroll
    for (int kk = 0; kk < 16; kk++) {
        ulonglong2 aA = *(const ulonglong2*)&As[kk][ty * 8];
        ulonglong2 aB = *(const ulonglong2*)&As[kk][ty * 8 + 4];
        ulonglong2 bA = *(const ulonglong2*)&Bs[kk][tx * 8];
        ulonglong2 bB = *(const ulonglong2*)&Bs[kk][tx * 8 + 4];
        FMA2(acc[0][0], aA.x, bA.x); FMA2(acc[0][1], aA.x, bA.y);
        FMA2(acc[0][2], aA.x, bB.x); FMA2(acc[0][3], aA.x, bB.y);
        FMA2(acc[1][0], aA.y, bA.x); FMA2(acc[1][1], aA.y, bA.y);
        FMA2(acc[1][2], aA.y, bB.x); FMA2(acc[1][3], aA.y, bB.y);
        FMA2(acc[2][0], aB.x, bA.x); FMA2(acc[2][1], aB.x, bA.y);
        FMA2(acc[2][2], aB.x, bB.x); FMA2(acc[2][3], aB.x, bB.y);
        FMA2(acc[3][0], aB.y, bA.x); FMA2(acc[3][1], aB.y, bA.y);
        FMA2(acc[3][2], aB.y, bB.x); FMA2(acc[3][3], aB.y, bB.y);
    }

    bool partial = (gridDim.z > 1);
    #pragma unroll
    for (int i2 = 0; i2 < 4; i2++) {
        int n0 = bn + ty * 8 + 2 * i2;
        #pragma unroll
        for (int j = 0; j < 4; j++) {
            int o = bo + tx * 4 + j;
            unsigned long long v = acc[i2][j];
            float lo = __uint_as_float((unsigned)(v & 0xffffffffu));
            float hi = __uint_as_float((unsigned)(v >> 32));
            if (partial) {
                *(float2*)&out[((size_t)blockIdx.z * Cout + o) * N + n0] = make_float2(lo, hi);
            } else {
                int b = n0 / HW, pos = n0 % HW;
                *(float2*)&out[((size_t)b * Cout + o) * HW + pos] =
                    make_float2(fmaxf(lo, 0.f), fmaxf(hi, 0.f));
            }
        }
    }
}

// ---------------- split-K reduce + ReLU -> activation layout ----------------
__global__ void reduceK(const float* __restrict__ part, float* __restrict__ out,
                        int Cout, int N, int HW, int nslab) {
    int t = blockIdx.x * blockDim.x + threadIdx.x;
    if (t >= Cout * N) return;
    int o = t / N, n = t % N;
    float s = 0.f;
    for (int z = 0; z < nslab; z++)
        s += part[((size_t)z * Cout + o) * N + n];
    int b = n / HW, pos = n % HW;
    out[((size_t)b * Cout + o) * HW + pos] = fmaxf(s, 0.f);
}

// ---------------- 2x2 maxpool ----------------
__global__ void maxpool2(const float* __restrict__ in, float* __restrict__ out, int C, int H) {
    int Ho = H >> 1;
    int total = BATCH * C * Ho * Ho;
    int t = blockIdx.x * blockDim.x + threadIdx.x;
    if (t >= total) return;
    int xo = t % Ho;
    int tmp = t / Ho;
    int yo = tmp % Ho;
    int bc = tmp / Ho;
    const float* p = in + ((size_t)bc * H + 2 * yo) * H + 2 * xo;
    out[t] = fmaxf(fmaxf(p[0], p[1]), fmaxf(p[H], p[H + 1]));
}

// ---------------- 4x4 average pool -> (B,512) ----------------
__global__ void avgpool4(const float* __restrict__ in, float* __restrict__ out) {
    int t = blockIdx.x * blockDim.x + threadIdx.x;
    if (t >= BATCH * 512) return;
    const float* p = in + (size_t)t * 16;
    float s = 0.f;
    #pragma unroll
    for (int i = 0; i < 16; i++) s += p[i];
    out[t] = s * (1.f / 16.f);
}

// ---------------- FC: warp per output neuron, all 8 batches ----------------
__global__ void fc_kernel(const float* __restrict__ v, const float* __restrict__ Wf,
                          const float* __restrict__ bias, float* __restrict__ out,
                          int In, int Out, int doRelu) {
    int warp = (blockIdx.x * blockDim.x + threadIdx.x) >> 5;
    int lane = threadIdx.x & 31;
    if (warp >= Out) return;
    const float* wrow = Wf + (size_t)warp * In;
    float acc[BATCH];
    #pragma unroll
    for (int b = 0; b < BATCH; b++) acc[b] = 0.f;
    for (int i = lane; i < In; i += 32) {
        float wv = wrow[i];
        #pragma unroll
        for (int b = 0; b < BATCH; b++)
            acc[b] = fmaf(wv, v[b * In + i], acc[b]);
    }
    #pragma unroll
    for (int b = 0; b < BATCH; b++) {
        #pragma unroll
        for (int off = 16; off; off >>= 1)
            acc[b] += __shfl_xor_sync(0xffffffffu, acc[b], off);
    }
    if (lane == 0) {
        float bi = bias[warp];
        #pragma unroll
        for (int b = 0; b < BATCH; b++) {
            float r = acc[b] + bi;
            if (doRelu) r = fmaxf(r, 0.f);
            out[b * Out + warp] = r;
        }
    }
}

// ---------------- host orchestration ----------------
static void conv_layer(const float* in, float* out, const float* wt, float* col,
                       float* part, int Cin, int Cout, int H, int tabBase, int nsplit) {
    int HW = H * H;
    int N = BATCH * HW;
    int K = Cin * 9;
    dim3 gi((N + 255) / 256, 9);
    im2col_deform<<<gi, 256>>>(in, col, Cin, HW, N, tabBase);
    if (nsplit == 1) {
        dim3 gg(N / 128, Cout / 64, 1);
        gemm_f32x2<<<gg, 256>>>(col, wt, out, N, K, K, Cout, HW);
    } else {
        int chunk = (K + nsplit - 1) / nsplit;
        dim3 gg(N / 128, Cout / 64, nsplit);
        gemm_f32x2<<<gg, 256>>>(col, wt, part, N, K, chunk, Cout, HW);
        reduceK<<<(Cout * N + 255) / 256, 256>>>(part, out, Cout, N, HW, nsplit);
    }
}

extern "C" void kernel_launch(void* const* d_in, const int* in_sizes, int n_in,
                              void* d_out, int out_size) {
    const float* x = (const float*)d_in[0];
    const float* w11 = (const float*)d_in[1];
    const float* w12 = (const float*)d_in[2];
    const float* w21 = (const float*)d_in[3];
    const float* w22 = (const float*)d_in[4];
    const float* w31 = (const float*)d_in[5];
    const float* w32 = (const float*)d_in[6];
    const float* w33 = (const float*)d_in[7];
    const float* w41 = (const float*)d_in[8];
    const float* w42 = (const float*)d_in[9];
    const float* w43 = (const float*)d_in[10];
    const float* w51 = (const float*)d_in[11];
    const float* w52 = (const float*)d_in[12];
    const float* w53 = (const float*)d_in[13];
    const float* fc1w = (const float*)d_in[14];
    const float* fc1b = (const float*)d_in[15];
    const float* fc2w = (const float*)d_in[16];
    const float* fc2b = (const float*)d_in[17];
    const float* fc3w = (const float*)d_in[18];
    const float* fc3b = (const float*)d_in[19];
    float* outp = (float*)d_out;

    float *bufA, *bufB, *col, *part, *vec1, *vec2;
    cudaGetSymbolAddress((void**)&bufA, g_bufA);
    cudaGetSymbolAddress((void**)&bufB, g_bufB);
    cudaGetSymbolAddress((void**)&col,  g_col);
    cudaGetSymbolAddress((void**)&part, g_part);
    cudaGetSymbolAddress((void**)&vec1, g_vec1);
    cudaGetSymbolAddress((void**)&vec2, g_vec2);

    // TB128 first, then conv1_1 so the ncu -s5 capture lands on the conv1_2 GEMM
    build_tab<<<(128*128*9 + 255) / 256, 256>>>(128, TB128);
    // block 1 (128x128)
    conv_layer(x,    bufA, w11, col, part,   3,  64, 128, TB128, 1);   // launches 2,3
    {   // conv1_2 split so its GEMM is launch #6 under ncu -s 5
        int HW = 128*128, N = BATCH*HW, K = 64*9;
        dim3 gi((N + 255) / 256, 9);
        im2col_deform<<<gi, 256>>>(bufA, col, 64, HW, N, TB128);       // launch 4
        build_tab<<<(64*64*9 + 255) / 256, 256>>>(64, TB64);           // launch 5
        dim3 gg(N / 128, 64 / 64, 1);
        gemm_f32x2<<<gg, 256>>>(col, w12, bufB, N, K, K, 64, HW);      // launch 6 (profiled)
    }
    build_tab<<<(32*32*9 + 255) / 256, 256>>>(32, TB32);
    build_tab<<<(16*16*9 + 255) / 256, 256>>>(16, TB16);
    build_tab<<<(8*8*9   + 255) / 256, 256>>>(8,  TB8);
    maxpool2<<<(BATCH*64*64*64 + 255) / 256, 256>>>(bufB, bufA, 64, 128);
    // block 2 (64x64)
    conv_layer(bufA, bufB, w21, col, part,  64, 128, 64, TB64, 1);
    conv_layer(bufB, bufA, w22, col, part, 128, 128, 64, TB64, 1);
    maxpool2<<<(BATCH*128*32*32 + 255) / 256, 256>>>(bufA, bufB, 128, 64);
    // block 3 (32x32)
    conv_layer(bufB, bufA, w31, col, part, 128, 256, 32, TB32, 1);
    conv_layer(bufA, bufB, w32, col, part, 256, 256, 32, TB32, 1);
    conv_layer(bufB, bufA, w33, col, part, 256, 256, 32, TB32, 1);
    maxpool2<<<(BATCH*256*16*16 + 255) / 256, 256>>>(bufA, bufB, 256, 32);
    // block 4 (16x16)
    conv_layer(bufB, bufA, w41, col, part, 256, 512, 16, TB16, 1);
    conv_layer(bufA, bufB, w42, col, part, 512, 512, 16, TB16, 1);
    conv_layer(bufB, bufA, w43, col, part, 512, 512, 16, TB16, 1);
    maxpool2<<<(BATCH*512*8*8 + 255) / 256, 256>>>(bufA, bufB, 512, 16);
    // block 5 (8x8) — split-K=4 to fill the chip
    conv_layer(bufB, bufA, w51, col, part, 512, 512, 8, TB8, 4);
    conv_layer(bufA, bufB, w52, col, part, 512, 512, 8, TB8, 4);
    conv_layer(bufB, bufA, w53, col, part, 512, 512, 8, TB8, 4);
    maxpool2<<<(BATCH*512*4*4 + 255) / 256, 256>>>(bufA, bufB, 512, 8);

    // head
    avgpool4<<<(BATCH*512 + 255) / 256, 256>>>(bufB, vec1);
    fc_kernel<<<(4096*32 + 255) / 256, 256>>>(vec1, fc1w, fc1b, vec2, 512, 4096, 1);
    fc_kernel<<<(4096*32 + 255) / 256, 256>>>(vec2, fc2w, fc2b, vec1, 4096, 4096, 1);
    fc_kernel<<<(30*32   + 255) / 256, 256>>>(vec1, fc3w, fc3b, outp, 4096, 30, 0);
}

// round 5
// speedup vs baseline: 1.2306x; 1.2306x over previous
#include <cuda_runtime.h>
#include <cuda_bf16.h>
#include <cstdint>

#define BATCH 8

// ---------------- scratch ----------------
__device__ float g_bufA[8u*64u*128u*128u];
__device__ float g_bufB[8u*64u*128u*128u];
__device__ __nv_bfloat16 g_colH[75497472u];   // [n][Kpad] hi plane (max conv1_2: 131072 x 576)
__device__ __nv_bfloat16 g_colL[75497472u];   // lo plane
__device__ __nv_bfloat16 g_wH[2359296u];      // weights hi  [O][Kpad] (max 512 x 4608)
__device__ __nv_bfloat16 g_wL[2359296u];
__device__ float g_part[4u*512u*512u];
__device__ int4   g_tabI[196416];
__device__ float4 g_tabW[196416];
__device__ float g_vec1[8*4096];
__device__ float g_vec2[8*4096];

#define TB128 0
#define TB64  147456
#define TB32  184320
#define TB16  193536
#define TB8   195840

// ---------------- PTX helpers (family-common: sm_80+ only) ----------------
__device__ __forceinline__ uint32_t s2u(const void* p) {
    uint32_t a;
    asm("{ .reg .u64 t; cvta.to.shared.u64 t, %1; cvt.u32.u64 %0, t; }" : "=r"(a) : "l"(p));
    return a;
}
#define CPA(dst, src) asm volatile("cp.async.cg.shared.global [%0], [%1], 16;" :: "r"(dst), "l"(src))
#define CPA_COMMIT()  asm volatile("cp.async.commit_group;" ::: "memory")
#define CPA_WAIT0()   asm volatile("cp.async.wait_group 0;" ::: "memory")
#define LDM4(r, addr) asm volatile("ldmatrix.sync.aligned.m8n8.x4.shared.b16 {%0,%1,%2,%3}, [%4];" \
    : "=r"((r)[0]), "=r"((r)[1]), "=r"((r)[2]), "=r"((r)[3]) : "r"(addr))
#define MMA(d, a, b) asm volatile( \
    "mma.sync.aligned.m16n8k16.row.col.f32.bf16.bf16.f32 {%0,%1,%2,%3},{%4,%5,%6,%7},{%8,%9},{%0,%1,%2,%3};" \
    : "+f"((d)[0]), "+f"((d)[1]), "+f"((d)[2]), "+f"((d)[3]) \
    : "r"((a)[0]), "r"((a)[1]), "r"((a)[2]), "r"((a)[3]), "r"((b)[0]), "r"((b)[1]))

// ---------------- offset table construction ----------------
__global__ void build_tab(int H, int base) {
    int t = blockIdx.x * blockDim.x + threadIdx.x;
    int HW = H * H;
    if (t >= HW * 9) return;
    int k = t % 9, pos = t / 9;
    int y = pos / H, x = pos % H;

    float cc = 0.5f * (float)H - 0.5f;
    float th = atan2f((float)x - cc, (float)y - cc);
    if (th < 0.f) th += 6.28318530717958647692f;
    th = rintf(th * 10000.0f) / 10000.0f;

    int ky = k / 3, kx = k % 3;
    float offy = 0.f, offx = 0.f;
    if (k != 4) {
        int m = (k < 4) ? k : k - 1;
        float ang = th + (float)(3.14159265358979323846 * 0.25 * (double)m);
        offy = cosf(ang) + (float)(1 - ky);
        offx = sinf(ang) + (float)(1 - kx);
    }
    float py = (float)(y - 1 + ky) + offy;
    float px = (float)(x - 1 + kx) + offx;
    float y0 = floorf(py), x0 = floorf(px);
    float fy = py - y0, fx = px - x0;
    float Hm = (float)(H - 1);

    float ys[2] = {y0, y0 + 1.f};
    float xs[2] = {x0, x0 + 1.f};
    float wy[2] = {1.f - fy, fy};
    float wx[2] = {1.f - fx, fx};

    int ids[4]; float ws[4]; int q = 0;
    #pragma unroll
    for (int iy = 0; iy < 2; iy++) {
        #pragma unroll
        for (int ix = 0; ix < 2; ix++) {
            float yf = ys[iy], xf = xs[ix];
            bool v = (yf >= 0.f) && (yf <= Hm) && (xf >= 0.f) && (xf <= Hm);
            int yi = (int)fminf(fmaxf(yf, 0.f), Hm);
            int xi = (int)fminf(fmaxf(xf, 0.f), Hm);
            ids[q] = yi * H + xi;
            ws[q]  = v ? (wy[iy] * wx[ix]) : 0.f;
            q++;
        }
    }
    g_tabI[base + t] = make_int4(ids[0], ids[1], ids[2], ids[3]);
    g_tabW[base + t] = make_float4(ws[0], ws[1], ws[2], ws[3]);
}

// ---------------- deformable im2col -> bf16 hi/lo, [n][Kpad] K-major ----------------
__global__ void im2col_tc(const float* __restrict__ x, __nv_bfloat16* __restrict__ colH,
                          __nv_bfloat16* __restrict__ colL, int Cin, int HW, int Ntot,
                          int Kpad, int tabBase) {
    int t = blockIdx.x * blockDim.x + threadIdx.x;
    if (t >= Ntot * Cin) return;
    int c = t % Cin, n = t / Cin;
    int pos = n % HW, b = n / HW;
    const float* xc = x + ((size_t)b * Cin + c) * HW;
    size_t base = (size_t)n * Kpad + c * 9;
    const int4*   tI = g_tabI + tabBase + pos * 9;
    const float4* tW = g_tabW + tabBase + pos * 9;
    #pragma unroll
    for (int k = 0; k < 9; k++) {
        int4 id = tI[k]; float4 w = tW[k];
        float v = xc[id.x] * w.x + xc[id.y] * w.y + xc[id.z] * w.z + xc[id.w] * w.w;
        __nv_bfloat16 h = __float2bfloat16(v);
        colH[base + k] = h;
        colL[base + k] = __float2bfloat16(v - __bfloat162float(h));
    }
}

__global__ void padK(__nv_bfloat16* __restrict__ colH, __nv_bfloat16* __restrict__ colL,
                     int Ntot, int Kpad, int Kreal) {
    int n = blockIdx.x * blockDim.x + threadIdx.x;
    if (n >= Ntot) return;
    size_t base = (size_t)n * Kpad;
    for (int k = Kreal; k < Kpad; k++) {
        colH[base + k] = __float2bfloat16(0.f);
        colL[base + k] = __float2bfloat16(0.f);
    }
}

// ---------------- weight fp32 -> bf16 hi/lo, zero-padded to Kpad ----------------
__global__ void convW(const float* __restrict__ W, __nv_bfloat16* __restrict__ wH,
                      __nv_bfloat16* __restrict__ wL, int O, int Kreal, int Kpad) {
    int t = blockIdx.x * blockDim.x + threadIdx.x;
    if (t >= O * Kpad) return;
    int o = t / Kpad, k = t % Kpad;
    float w = (k < Kreal) ? W[(size_t)o * Kreal + k] : 0.f;
    __nv_bfloat16 h = __float2bfloat16(w);
    wH[t] = h;
    wL[t] = __float2bfloat16(w - __bfloat162float(h));
}

// ---------------- HMMA GEMM: 128x64x32 tiles, bf16 hi/lo, cp.async double buffer ----------------
// smem stage (elements): AH@0 (128*40), AL@5120, BH@10240 (64*40), BL@12800; stage=15360 el=30720B
#define RS 40
#define STAGE_B 30720
#define SMEM_TOT 61440
__global__ void __launch_bounds__(256) gemm_mma(
    const __nv_bfloat16* __restrict__ AH, const __nv_bfloat16* __restrict__ AL,
    const __nv_bfloat16* __restrict__ WH, const __nv_bfloat16* __restrict__ WL,
    float* __restrict__ out, float* __restrict__ part,
    int Ntot, int Kpad, int chunkK, int Cout, int HW) {
    extern __shared__ char smem[];
    uint32_t sb0 = s2u(smem);
    int tid = threadIdx.x, l = tid & 31, wid = tid >> 5;
    int wm = wid & 3, wn = wid >> 2;
    int bn = blockIdx.x * 128, bo = blockIdx.y * 64;
    int kStart = blockIdx.z * chunkK;
    int nk = chunkK >> 5;

    float acc[2][4][4];
    #pragma unroll
    for (int i = 0; i < 2; i++)
        #pragma unroll
        for (int j = 0; j < 4; j++)
            #pragma unroll
            for (int q = 0; q < 4; q++) acc[i][j][q] = 0.f;

    // stage loader
    auto load_stage = [&](int st, int k0) {
        uint32_t sb = sb0 + st * STAGE_B;
        #pragma unroll
        for (int i = 0; i < 4; i++) {
            int u = tid + i * 256;
            int plane = u >> 9, row = (u >> 2) & 127, c = u & 3;
            const __nv_bfloat16* src = (plane ? AL : AH) + (size_t)(bn + row) * Kpad + k0 + c * 8;
            uint32_t dst = sb + (uint32_t)(plane * 5120 + row * RS + c * 8) * 2;
            CPA(dst, src);
        }
        #pragma unroll
        for (int i = 0; i < 2; i++) {
            int u = tid + i * 256;
            int plane = u >> 8, row = (u >> 2) & 63, c = u & 3;
            const __nv_bfloat16* src = (plane ? WL : WH) + (size_t)(bo + row) * Kpad + k0 + c * 8;
            uint32_t dst = sb + (uint32_t)(10240 + plane * 2560 + row * RS + c * 8) * 2;
            CPA(dst, src);
        }
        CPA_COMMIT();
    };

    load_stage(0, kStart);

    for (int it = 0; it < nk; it++) {
        CPA_WAIT0();
        __syncthreads();
        if (it + 1 < nk) load_stage((it + 1) & 1, kStart + (it + 1) * 32);

        uint32_t base = sb0 + (it & 1) * STAGE_B;
        #pragma unroll
        for (int ks = 0; ks < 2; ks++) {
            uint32_t aH[2][4], aL[2][4], bH[4][2], bL[4][2];
            #pragma unroll
            for (int mi = 0; mi < 2; mi++) {
                int row = wm * 32 + mi * 16 + (l & 15);
                uint32_t off = (uint32_t)(row * RS + ks * 16 + (l >> 4) * 8) * 2;
                LDM4(aH[mi], base + off);
                LDM4(aL[mi], base + 10240 + off);
            }
            #pragma unroll
            for (int j = 0; j < 2; j++) {
                int row = wn * 32 + j * 16 + (l & 7) + ((l >> 4) << 3);
                uint32_t off = (uint32_t)(10240 + row * RS + ks * 16 + ((l >> 3) & 1) * 8) * 2;
                uint32_t r[4];
                LDM4(r, base + off);
                bH[2*j][0] = r[0]; bH[2*j][1] = r[1]; bH[2*j+1][0] = r[2]; bH[2*j+1][1] = r[3];
                LDM4(r, base + off + 5120);
                bL[2*j][0] = r[0]; bL[2*j][1] = r[1]; bL[2*j+1][0] = r[2]; bL[2*j+1][1] = r[3];
            }
            #pragma unroll
            for (int mi = 0; mi < 2; mi++)
                #pragma unroll
                for (int nf = 0; nf < 4; nf++) {
                    MMA(acc[mi][nf], aH[mi], bH[nf]);
                    MMA(acc[mi][nf], aH[mi], bL[nf]);
                    MMA(acc[mi][nf], aL[mi], bH[nf]);
                }
        }
        __syncthreads();
    }

    bool dosplit = (gridDim.z > 1);
    #pragma unroll
    for (int mi = 0; mi < 2; mi++)
        #pragma unroll
        for (int nf = 0; nf < 4; nf++) {
            int row0 = bn + wm * 32 + mi * 16 + (l >> 2);
            int col0 = bo + wn * 32 + nf * 8 + 2 * (l & 3);
            float* d = acc[mi][nf];
            if (dosplit) {
                size_t zb = (size_t)blockIdx.z * Cout;
                part[(zb + col0)     * Ntot + row0]     = d[0];
                part[(zb + col0 + 1) * Ntot + row0]     = d[1];
                part[(zb + col0)     * Ntot + row0 + 8] = d[2];
                part[(zb + col0 + 1) * Ntot + row0 + 8] = d[3];
            } else {
                int b0 = row0 / HW, p0 = row0 % HW;
                int r1 = row0 + 8;
                int b1 = r1 / HW, p1 = r1 % HW;
                out[((size_t)b0 * Cout + col0)     * HW + p0] = fmaxf(d[0], 0.f);
                out[((size_t)b0 * Cout + col0 + 1) * HW + p0] = fmaxf(d[1], 0.f);
                out[((size_t)b1 * Cout + col0)     * HW + p1] = fmaxf(d[2], 0.f);
                out[((size_t)b1 * Cout + col0 + 1) * HW + p1] = fmaxf(d[3], 0.f);
            }
        }
}

// ---------------- split-K reduce + ReLU ----------------
__global__ void reduceK(const float* __restrict__ part, float* __restrict__ out,
                        int Cout, int N, int HW, int nslab) {
    int t = blockIdx.x * blockDim.x + threadIdx.x;
    if (t >= Cout * N) return;
    int o = t / N, n = t % N;
    float s = 0.f;
    for (int z = 0; z < nslab; z++)
        s += part[((size_t)z * Cout + o) * N + n];
    int b = n / HW, pos = n % HW;
    out[((size_t)b * Cout + o) * HW + pos] = fmaxf(s, 0.f);
}

// ---------------- pools / FC ----------------
__global__ void maxpool2(const float* __restrict__ in, float* __restrict__ out, int C, int H) {
    int Ho = H >> 1;
    int total = BATCH * C * Ho * Ho;
    int t = blockIdx.x * blockDim.x + threadIdx.x;
    if (t >= total) return;
    int xo = t % Ho;
    int tmp = t / Ho;
    int yo = tmp % Ho;
    int bc = tmp / Ho;
    const float* p = in + ((size_t)bc * H + 2 * yo) * H + 2 * xo;
    out[t] = fmaxf(fmaxf(p[0], p[1]), fmaxf(p[H], p[H + 1]));
}

__global__ void avgpool4(const float* __restrict__ in, float* __restrict__ out) {
    int t = blockIdx.x * blockDim.x + threadIdx.x;
    if (t >= BATCH * 512) return;
    const float* p = in + (size_t)t * 16;
    float s = 0.f;
    #pragma unroll
    for (int i = 0; i < 16; i++) s += p[i];
    out[t] = s * (1.f / 16.f);
}

__global__ void fc_kernel(const float* __restrict__ v, const float* __restrict__ Wf,
                          const float* __restrict__ bias, float* __restrict__ out,
                          int In, int Out, int doRelu) {
    int warp = (blockIdx.x * blockDim.x + threadIdx.x) >> 5;
    int lane = threadIdx.x & 31;
    if (warp >= Out) return;
    const float* wrow = Wf + (size_t)warp * In;
    float acc[BATCH];
    #pragma unroll
    for (int b = 0; b < BATCH; b++) acc[b] = 0.f;
    for (int i = lane; i < In; i += 32) {
        float wv = wrow[i];
        #pragma unroll
        for (int b = 0; b < BATCH; b++)
            acc[b] = fmaf(wv, v[b * In + i], acc[b]);
    }
    #pragma unroll
    for (int b = 0; b < BATCH; b++) {
        #pragma unroll
        for (int off = 16; off; off >>= 1)
            acc[b] += __shfl_xor_sync(0xffffffffu, acc[b], off);
    }
    if (lane == 0) {
        float bi = bias[warp];
        #pragma unroll
        for (int b = 0; b < BATCH; b++) {
            float r = acc[b] + bi;
            if (doRelu) r = fmaxf(r, 0.f);
            out[b * Out + warp] = r;
        }
    }
}

// ---------------- host ----------------
struct Bufs {
    float *bufA, *bufB, *part, *vec1, *vec2;
    __nv_bfloat16 *colH, *colL, *wH, *wL;
};

static void conv_tc(const Bufs& B, const float* in, float* out, const float* wt,
                    int Cin, int Cout, int H, int tabBase, int nsplit) {
    int HW = H * H;
    int Ntot = BATCH * HW;
    int Kreal = Cin * 9;
    int Kpad = (Kreal + 31) & ~31;
    im2col_tc<<<(Ntot * Cin + 255) / 256, 256>>>(in, B.colH, B.colL, Cin, HW, Ntot, Kpad, tabBase);
    if (Kpad != Kreal)
        padK<<<(Ntot + 255) / 256, 256>>>(B.colH, B.colL, Ntot, Kpad, Kreal);
    convW<<<(Cout * Kpad + 255) / 256, 256>>>(wt, B.wH, B.wL, Cout, Kreal, Kpad);
    dim3 gg(Ntot / 128, Cout / 64, nsplit);
    gemm_mma<<<gg, 256, SMEM_TOT>>>(B.colH, B.colL, B.wH, B.wL, out, B.part,
                                    Ntot, Kpad, Kpad / nsplit, Cout, HW);
    if (nsplit > 1)
        reduceK<<<(Cout * Ntot + 255) / 256, 256>>>(B.part, out, Cout, Ntot, HW, nsplit);
}

extern "C" void kernel_launch(void* const* d_in, const int* in_sizes, int n_in,
                              void* d_out, int out_size) {
    const float* x   = (const float*)d_in[0];
    const float* w11 = (const float*)d_in[1];
    const float* w12 = (const float*)d_in[2];
    const float* w21 = (const float*)d_in[3];
    const float* w22 = (const float*)d_in[4];
    const float* w31 = (const float*)d_in[5];
    const float* w32 = (const float*)d_in[6];
    const float* w33 = (const float*)d_in[7];
    const float* w41 = (const float*)d_in[8];
    const float* w42 = (const float*)d_in[9];
    const float* w43 = (const float*)d_in[10];
    const float* w51 = (const float*)d_in[11];
    const float* w52 = (const float*)d_in[12];
    const float* w53 = (const float*)d_in[13];
    const float* fc1w = (const float*)d_in[14];
    const float* fc1b = (const float*)d_in[15];
    const float* fc2w = (const float*)d_in[16];
    const float* fc2b = (const float*)d_in[17];
    const float* fc3w = (const float*)d_in[18];
    const float* fc3b = (const float*)d_in[19];
    float* outp = (float*)d_out;

    Bufs B;
    cudaGetSymbolAddress((void**)&B.bufA, g_bufA);
    cudaGetSymbolAddress((void**)&B.bufB, g_bufB);
    cudaGetSymbolAddress((void**)&B.part, g_part);
    cudaGetSymbolAddress((void**)&B.vec1, g_vec1);
    cudaGetSymbolAddress((void**)&B.vec2, g_vec2);
    cudaGetSymbolAddress((void**)&B.colH, g_colH);
    cudaGetSymbolAddress((void**)&B.colL, g_colL);
    cudaGetSymbolAddress((void**)&B.wH,  g_wH);
    cudaGetSymbolAddress((void**)&B.wL,  g_wL);

    cudaFuncSetAttribute(gemm_mma, cudaFuncAttributeMaxDynamicSharedMemorySize, SMEM_TOT);

    // launch order: #6 = im2col of conv1_2 (profiled under ncu -s5 -c1)
    build_tab<<<(128*128*9 + 255) / 256, 256>>>(128, TB128);            // 1
    conv_tc(B, x, B.bufA, w11, 3, 64, 128, TB128, 1);                   // 2 im2col, 3 padK, 4 convW, 5 gemm
    conv_tc(B, B.bufA, B.bufB, w12, 64, 64, 128, TB128, 1);             // 6 im2col (profiled), 7 convW, 8 gemm
    build_tab<<<(64*64*9 + 255) / 256, 256>>>(64, TB64);
    build_tab<<<(32*32*9 + 255) / 256, 256>>>(32, TB32);
    build_tab<<<(16*16*9 + 255) / 256, 256>>>(16, TB16);
    build_tab<<<(8*8*9 + 255) / 256, 256>>>(8, TB8);
    maxpool2<<<(BATCH*64*64*64 + 255) / 256, 256>>>(B.bufB, B.bufA, 64, 128);

    conv_tc(B, B.bufA, B.bufB, w21, 64, 128, 64, TB64, 1);
    conv_tc(B, B.bufB, B.bufA, w22, 128, 128, 64, TB64, 1);
    maxpool2<<<(BATCH*128*32*32 + 255) / 256, 256>>>(B.bufA, B.bufB, 128, 64);

    conv_tc(B, B.bufB, B.bufA, w31, 128, 256, 32, TB32, 1);
    conv_tc(B, B.bufA, B.bufB, w32, 256, 256, 32, TB32, 1);
    conv_tc(B, B.bufB, B.bufA, w33, 256, 256, 32, TB32, 1);
    maxpool2<<<(BATCH*256*16*16 + 255) / 256, 256>>>(B.bufA, B.bufB, 256, 32);

    conv_tc(B, B.bufB, B.bufA, w41, 256, 512, 16, TB16, 1);
    conv_tc(B, B.bufA, B.bufB, w42, 512, 512, 16, TB16, 1);
    conv_tc(B, B.bufB, B.bufA, w43, 512, 512, 16, TB16, 1);
    maxpool2<<<(BATCH*512*8*8 + 255) / 256, 256>>>(B.bufA, B.bufB, 512, 16);

    conv_tc(B, B.bufB, B.bufA, w51, 512, 512, 8, TB8, 4);
    conv_tc(B, B.bufA, B.bufB, w52, 512, 512, 8, TB8, 4);
    conv_tc(B, B.bufB, B.bufA, w53, 512, 512, 8, TB8, 4);
    maxpool2<<<(BATCH*512*4*4 + 255) / 256, 256>>>(B.bufA, B.bufB, 512, 8);

    avgpool4<<<(BATCH*512 + 255) / 256, 256>>>(B.bufB, B.vec1);
    fc_kernel<<<(4096*32 + 255) / 256, 256>>>(B.vec1, fc1w, fc1b, B.vec2, 512, 4096, 1);
    fc_kernel<<<(4096*32 + 255) / 256, 256>>>(B.vec2, fc2w, fc2b, B.vec1, 4096, 4096, 1);
    fc_kernel<<<(30*32 + 255) / 256, 256>>>(B.vec1, fc3w, fc3b, outp, 4096, 30, 0);
}

// round 6
// speedup vs baseline: 2.8515x; 2.3171x over previous
#include <cuda_runtime.h>
#include <cuda_bf16.h>
#include <cstdint>

#define BATCH 8

// ---------------- scratch ----------------
__device__ float g_bufA[8u*64u*128u*128u];
__device__ float g_bufB[8u*64u*128u*128u];
__device__ __nv_bfloat16 g_colH[75497472u];   // [k][n] hi plane (max conv1_2: 576 x 131072)
__device__ __nv_bfloat16 g_colL[75497472u];   // lo plane
__device__ __nv_bfloat16 g_wH[2359296u];      // weights hi [O][Kpad]
__device__ __nv_bfloat16 g_wL[2359296u];
__device__ float g_part[4u*512u*512u];
__device__ int4   g_tabI[196416];
__device__ float4 g_tabW[196416];
__device__ float g_vec1[8*4096];
__device__ float g_vec2[8*4096];

#define TB128 0
#define TB64  147456
#define TB32  184320
#define TB16  193536
#define TB8   195840

// ---------------- PTX helpers (family-common sm_80+) ----------------
__device__ __forceinline__ uint32_t s2u(const void* p) {
    uint32_t a;
    asm("{ .reg .u64 t; cvta.to.shared.u64 t, %1; cvt.u32.u64 %0, t; }" : "=r"(a) : "l"(p));
    return a;
}
#define CPA(dst, src) asm volatile("cp.async.cg.shared.global [%0], [%1], 16;" :: "r"(dst), "l"(src))
#define CPA_COMMIT()  asm volatile("cp.async.commit_group;" ::: "memory")
#define CPA_WAIT0()   asm volatile("cp.async.wait_group 0;" ::: "memory")
#define LDM4(r, addr) asm volatile("ldmatrix.sync.aligned.m8n8.x4.shared.b16 {%0,%1,%2,%3}, [%4];" \
    : "=r"((r)[0]), "=r"((r)[1]), "=r"((r)[2]), "=r"((r)[3]) : "r"(addr))
#define LDM4T(r, addr) asm volatile("ldmatrix.sync.aligned.m8n8.x4.trans.shared.b16 {%0,%1,%2,%3}, [%4];" \
    : "=r"((r)[0]), "=r"((r)[1]), "=r"((r)[2]), "=r"((r)[3]) : "r"(addr))
#define MMA(d, a, b) asm volatile( \
    "mma.sync.aligned.m16n8k16.row.col.f32.bf16.bf16.f32 {%0,%1,%2,%3},{%4,%5,%6,%7},{%8,%9},{%0,%1,%2,%3};" \
    : "+f"((d)[0]), "+f"((d)[1]), "+f"((d)[2]), "+f"((d)[3]) \
    : "r"((a)[0]), "r"((a)[1]), "r"((a)[2]), "r"((a)[3]), "r"((b)[0]), "r"((b)[1]))

// ---------------- tab build (device helper) ----------------
__device__ __forceinline__ void tab_one(int t, int H, int base) {
    int HW = H * H;
    if (t >= HW * 9) return;
    int k = t % 9, pos = t / 9;
    int y = pos / H, x = pos % H;

    float cc = 0.5f * (float)H - 0.5f;
    float th = atan2f((float)x - cc, (float)y - cc);
    if (th < 0.f) th += 6.28318530717958647692f;
    th = rintf(th * 10000.0f) / 10000.0f;

    int ky = k / 3, kx = k % 3;
    float offy = 0.f, offx = 0.f;
    if (k != 4) {
        int m = (k < 4) ? k : k - 1;
        float ang = th + (float)(3.14159265358979323846 * 0.25 * (double)m);
        offy = cosf(ang) + (float)(1 - ky);
        offx = sinf(ang) + (float)(1 - kx);
    }
    float py = (float)(y - 1 + ky) + offy;
    float px = (float)(x - 1 + kx) + offx;
    float y0 = floorf(py), x0 = floorf(px);
    float fy = py - y0, fx = px - x0;
    float Hm = (float)(H - 1);

    float ys[2] = {y0, y0 + 1.f};
    float xs[2] = {x0, x0 + 1.f};
    float wy[2] = {1.f - fy, fy};
    float wx[2] = {1.f - fx, fx};

    int ids[4]; float ws[4]; int q = 0;
    #pragma unroll
    for (int iy = 0; iy < 2; iy++) {
        #pragma unroll
        for (int ix = 0; ix < 2; ix++) {
            float yf = ys[iy], xf = xs[ix];
            bool v = (yf >= 0.f) && (yf <= Hm) && (xf >= 0.f) && (xf <= Hm);
            int yi = (int)fminf(fmaxf(yf, 0.f), Hm);
            int xi = (int)fminf(fmaxf(xf, 0.f), Hm);
            ids[q] = yi * H + xi;
            ws[q]  = v ? (wy[iy] * wx[ix]) : 0.f;
            q++;
        }
    }
    g_tabI[base + t] = make_int4(ids[0], ids[1], ids[2], ids[3]);
    g_tabW[base + t] = make_float4(ws[0], ws[1], ws[2], ws[3]);
}

__global__ void build_tab(int H, int base) {
    tab_one(blockIdx.x * blockDim.x + threadIdx.x, H, base);
}

// fused: build tab128 AND zero conv1_1's pad k-rows [27,32) of col planes
__global__ void prep128(__nv_bfloat16* colH, __nv_bfloat16* colL) {
    if (blockIdx.x < 576) {
        tab_one(blockIdx.x * 256 + threadIdx.x, 128, TB128);
    } else {
        int i = (blockIdx.x - 576) * 256 + threadIdx.x;   // over 5*131072
        if (i < 5 * 131072) {
            size_t off = (size_t)27 * 131072 + i;
            colH[off] = __float2bfloat16(0.f);
            colL[off] = __float2bfloat16(0.f);
        }
    }
}

// ---------------- deformable im2col -> bf16 hi/lo, [k][n] layout ----------------
// thread = position n (coalesced), blockIdx.y = tap, inner loop over channels
__global__ void im2col2(const float* __restrict__ x, __nv_bfloat16* __restrict__ colH,
                        __nv_bfloat16* __restrict__ colL, int Cin, int HW, int Ntot,
                        int tabBase) {
    int n = blockIdx.x * blockDim.x + threadIdx.x;   // Ntot is a multiple of 512
    int tap = blockIdx.y;
    int pos = n % HW, b = n / HW;
    int4   id = g_tabI[tabBase + pos * 9 + tap];
    float4 w  = g_tabW[tabBase + pos * 9 + tap];
    const float* xb = x + (size_t)b * Cin * HW;
    size_t cstep = (size_t)9 * Ntot;
    __nv_bfloat16* pH = colH + (size_t)tap * Ntot + n;
    __nv_bfloat16* pL = colL + (size_t)tap * Ntot + n;
    for (int c = 0; c < Cin; c++) {
        const float* xc = xb + (size_t)c * HW;
        float v = xc[id.x] * w.x + xc[id.y] * w.y + xc[id.z] * w.z + xc[id.w] * w.w;
        __nv_bfloat16 h = __float2bfloat16(v);
        pH[c * cstep] = h;
        pL[c * cstep] = __float2bfloat16(v - __bfloat162float(h));
    }
}

// ---------------- weight fp32 -> bf16 hi/lo, padded to Kpad ----------------
__global__ void convW(const float* __restrict__ W, __nv_bfloat16* __restrict__ wH,
                      __nv_bfloat16* __restrict__ wL, int O, int Kreal, int Kpad) {
    int t = blockIdx.x * blockDim.x + threadIdx.x;
    if (t >= O * Kpad) return;
    int o = t / Kpad, k = t % Kpad;
    float w = (k < Kreal) ? W[(size_t)o * Kreal + k] : 0.f;
    __nv_bfloat16 h = __float2bfloat16(w);
    wH[t] = h;
    wL[t] = __float2bfloat16(w - __bfloat162float(h));
}

// ---------------- HMMA GEMM 128x64x32, A in [k][n] via ldmatrix.trans ----------------
// smem stage bytes: AH@0 (32 k-rows x 136 el), AL@8704, BH@17408 (64 o x 40 el), BL@22528
#define RSA 136
#define RSB 40
#define OF_AL 8704
#define OF_B  17408
#define OF_BL 5120
#define STAGE_B 27648
#define SMEM_TOT 55296
__global__ void __launch_bounds__(256) gemm_mma(
    const __nv_bfloat16* __restrict__ AH, const __nv_bfloat16* __restrict__ AL,
    const __nv_bfloat16* __restrict__ WH, const __nv_bfloat16* __restrict__ WL,
    float* __restrict__ out, float* __restrict__ part,
    int Ntot, int Kpad, int chunkK, int Cout, int HW) {
    extern __shared__ char smem[];
    uint32_t sb0 = s2u(smem);
    int tid = threadIdx.x, l = tid & 31, wid = tid >> 5;
    int wm = wid & 3, wn = wid >> 2;
    int bn = blockIdx.x * 128, bo = blockIdx.y * 64;
    int kStart = blockIdx.z * chunkK;
    int nk = chunkK >> 5;

    float acc[2][4][4];
    #pragma unroll
    for (int i = 0; i < 2; i++)
        #pragma unroll
        for (int j = 0; j < 4; j++)
            #pragma unroll
            for (int q = 0; q < 4; q++) acc[i][j][q] = 0.f;

    auto load_stage = [&](int st, int k0) {
        uint32_t sb = sb0 + st * STAGE_B;
        // A: 2 planes x 32 k-rows x 16 chunks of 16B
        #pragma unroll
        for (int i = 0; i < 4; i++) {
            int u = tid + i * 256;
            int plane = u >> 9, rem = u & 511;
            int krow = rem >> 4, c = rem & 15;
            const __nv_bfloat16* src = (plane ? AL : AH) + (size_t)(k0 + krow) * Ntot + bn + c * 8;
            uint32_t dst = sb + plane * OF_AL + (uint32_t)(krow * RSA + c * 8) * 2;
            CPA(dst, src);
        }
        // B: 2 planes x 64 o-rows x 4 chunks of 16B (32 k)
        #pragma unroll
        for (int i = 0; i < 2; i++) {
            int u = tid + i * 256;
            int plane = u >> 8, rem = u & 255;
            int row = rem >> 2, c = rem & 3;
            const __nv_bfloat16* src = (plane ? WL : WH) + (size_t)(bo + row) * Kpad + k0 + c * 8;
            uint32_t dst = sb + OF_B + plane * OF_BL + (uint32_t)(row * RSB + c * 8) * 2;
            CPA(dst, src);
        }
        CPA_COMMIT();
    };

    load_stage(0, kStart);

    for (int it = 0; it < nk; it++) {
        CPA_WAIT0();
        __syncthreads();
        if (it + 1 < nk) load_stage((it + 1) & 1, kStart + (it + 1) * 32);

        uint32_t base = sb0 + (it & 1) * STAGE_B;
        // A trans-ldmatrix lane address components
        int krow = (l & 7) + ((l & 16) >> 1);     // 0..15
        int mcol = (l & 8);                        // 0 or 8
        #pragma unroll
        for (int ks = 0; ks < 2; ks++) {
            uint32_t aH[2][4], aL[2][4], bH[4][2], bL[4][2];
            #pragma unroll
            for (int mi = 0; mi < 2; mi++) {
                uint32_t off = (uint32_t)((ks * 16 + krow) * RSA + wm * 32 + mi * 16 + mcol) * 2;
                LDM4T(aH[mi], base + off);
                LDM4T(aL[mi], base + OF_AL + off);
            }
            #pragma unroll
            for (int j = 0; j < 2; j++) {
                int row = wn * 32 + j * 16 + (l & 7) + ((l >> 4) << 3);
                uint32_t off = OF_B + (uint32_t)(row * RSB + ks * 16 + ((l >> 3) & 1) * 8) * 2;
                uint32_t r[4];
                LDM4(r, base + off);
                bH[2*j][0] = r[0]; bH[2*j][1] = r[1]; bH[2*j+1][0] = r[2]; bH[2*j+1][1] = r[3];
                LDM4(r, base + off + OF_BL);
                bL[2*j][0] = r[0]; bL[2*j][1] = r[1]; bL[2*j+1][0] = r[2]; bL[2*j+1][1] = r[3];
            }
            #pragma unroll
            for (int mi = 0; mi < 2; mi++)
                #pragma unroll
                for (int nf = 0; nf < 4; nf++) {
                    MMA(acc[mi][nf], aH[mi], bH[nf]);
                    MMA(acc[mi][nf], aH[mi], bL[nf]);
                    MMA(acc[mi][nf], aL[mi], bH[nf]);
                }
        }
        __syncthreads();
    }

    bool dosplit = (gridDim.z > 1);
    #pragma unroll
    for (int mi = 0; mi < 2; mi++)
        #pragma unroll
        for (int nf = 0; nf < 4; nf++) {
            int row0 = bn + wm * 32 + mi * 16 + (l >> 2);
            int col0 = bo + wn * 32 + nf * 8 + 2 * (l & 3);
            float* d = acc[mi][nf];
            if (dosplit) {
                size_t zb = (size_t)blockIdx.z * Cout;
                part[(zb + col0)     * Ntot + row0]     = d[0];
                part[(zb + col0 + 1) * Ntot + row0]     = d[1];
                part[(zb + col0)     * Ntot + row0 + 8] = d[2];
                part[(zb + col0 + 1) * Ntot + row0 + 8] = d[3];
            } else {
                int b0 = row0 / HW, p0 = row0 % HW;
                int r1 = row0 + 8;
                int b1 = r1 / HW, p1 = r1 % HW;
                out[((size_t)b0 * Cout + col0)     * HW + p0] = fmaxf(d[0], 0.f);
                out[((size_t)b0 * Cout + col0 + 1) * HW + p0] = fmaxf(d[1], 0.f);
                out[((size_t)b1 * Cout + col0)     * HW + p1] = fmaxf(d[2], 0.f);
                out[((size_t)b1 * Cout + col0 + 1) * HW + p1] = fmaxf(d[3], 0.f);
            }
        }
}

// ---------------- split-K reduce + ReLU ----------------
__global__ void reduceK(const float* __restrict__ part, float* __restrict__ out,
                        int Cout, int N, int HW, int nslab) {
    int t = blockIdx.x * blockDim.x + threadIdx.x;
    if (t >= Cout * N) return;
    int o = t / N, n = t % N;
    float s = 0.f;
    for (int z = 0; z < nslab; z++)
        s += part[((size_t)z * Cout + o) * N + n];
    int b = n / HW, pos = n % HW;
    out[((size_t)b * Cout + o) * HW + pos] = fmaxf(s, 0.f);
}

// ---------------- pools / FC ----------------
__global__ void maxpool2(const float* __restrict__ in, float* __restrict__ out, int C, int H) {
    int Ho = H >> 1;
    int total = BATCH * C * Ho * Ho;
    int t = blockIdx.x * blockDim.x + threadIdx.x;
    if (t >= total) return;
    int xo = t % Ho;
    int tmp = t / Ho;
    int yo = tmp % Ho;
    int bc = tmp / Ho;
    const float* p = in + ((size_t)bc * H + 2 * yo) * H + 2 * xo;
    out[t] = fmaxf(fmaxf(p[0], p[1]), fmaxf(p[H], p[H + 1]));
}

__global__ void avgpool4(const float* __restrict__ in, float* __restrict__ out) {
    int t = blockIdx.x * blockDim.x + threadIdx.x;
    if (t >= BATCH * 512) return;
    const float* p = in + (size_t)t * 16;
    float s = 0.f;
    #pragma unroll
    for (int i = 0; i < 16; i++) s += p[i];
    out[t] = s * (1.f / 16.f);
}

__global__ void fc_kernel(const float* __restrict__ v, const float* __restrict__ Wf,
                          const float* __restrict__ bias, float* __restrict__ out,
                          int In, int Out, int doRelu) {
    int warp = (blockIdx.x * blockDim.x + threadIdx.x) >> 5;
    int lane = threadIdx.x & 31;
    if (warp >= Out) return;
    const float* wrow = Wf + (size_t)warp * In;
    float acc[BATCH];
    #pragma unroll
    for (int b = 0; b < BATCH; b++) acc[b] = 0.f;
    for (int i = lane; i < In; i += 32) {
        float wv = wrow[i];
        #pragma unroll
        for (int b = 0; b < BATCH; b++)
            acc[b] = fmaf(wv, v[b * In + i], acc[b]);
    }
    #pragma unroll
    for (int b = 0; b < BATCH; b++) {
        #pragma unroll
        for (int off = 16; off; off >>= 1)
            acc[b] += __shfl_xor_sync(0xffffffffu, acc[b], off);
    }
    if (lane == 0) {
        float bi = bias[warp];
        #pragma unroll
        for (int b = 0; b < BATCH; b++) {
            float r = acc[b] + bi;
            if (doRelu) r = fmaxf(r, 0.f);
            out[b * Out + warp] = r;
        }
    }
}

// ---------------- host ----------------
struct Bufs {
    float *bufA, *bufB, *part, *vec1, *vec2;
    __nv_bfloat16 *colH, *colL, *wH, *wL;
};

static void conv_tc(const Bufs& B, const float* in, float* out, const float* wt,
                    int Cin, int Cout, int H, int tabBase, int nsplit) {
    int HW = H * H;
    int Ntot = BATCH * HW;
    int Kreal = Cin * 9;
    int Kpad = (Kreal + 31) & ~31;
    im2col2<<<dim3(Ntot / 256, 9), 256>>>(in, B.colH, B.colL, Cin, HW, Ntot, tabBase);
    convW<<<(Cout * Kpad + 255) / 256, 256>>>(wt, B.wH, B.wL, Cout, Kreal, Kpad);
    dim3 gg(Ntot / 128, Cout / 64, nsplit);
    gemm_mma<<<gg, 256, SMEM_TOT>>>(B.colH, B.colL, B.wH, B.wL, out, B.part,
                                    Ntot, Kpad, Kpad / nsplit, Cout, HW);
    if (nsplit > 1)
        reduceK<<<(Cout * Ntot + 255) / 256, 256>>>(B.part, out, Cout, Ntot, HW, nsplit);
}

extern "C" void kernel_launch(void* const* d_in, const int* in_sizes, int n_in,
                              void* d_out, int out_size) {
    const float* x   = (const float*)d_in[0];
    const float* w11 = (const float*)d_in[1];
    const float* w12 = (const float*)d_in[2];
    const float* w21 = (const float*)d_in[3];
    const float* w22 = (const float*)d_in[4];
    const float* w31 = (const float*)d_in[5];
    const float* w32 = (const float*)d_in[6];
    const float* w33 = (const float*)d_in[7];
    const float* w41 = (const float*)d_in[8];
    const float* w42 = (const float*)d_in[9];
    const float* w43 = (const float*)d_in[10];
    const float* w51 = (const float*)d_in[11];
    const float* w52 = (const float*)d_in[12];
    const float* w53 = (const float*)d_in[13];
    const float* fc1w = (const float*)d_in[14];
    const float* fc1b = (const float*)d_in[15];
    const float* fc2w = (const float*)d_in[16];
    const float* fc2b = (const float*)d_in[17];
    const float* fc3w = (const float*)d_in[18];
    const float* fc3b = (const float*)d_in[19];
    float* outp = (float*)d_out;

    Bufs B;
    cudaGetSymbolAddress((void**)&B.bufA, g_bufA);
    cudaGetSymbolAddress((void**)&B.bufB, g_bufB);
    cudaGetSymbolAddress((void**)&B.part, g_part);
    cudaGetSymbolAddress((void**)&B.vec1, g_vec1);
    cudaGetSymbolAddress((void**)&B.vec2, g_vec2);
    cudaGetSymbolAddress((void**)&B.colH, g_colH);
    cudaGetSymbolAddress((void**)&B.colL, g_colL);
    cudaGetSymbolAddress((void**)&B.wH,  g_wH);
    cudaGetSymbolAddress((void**)&B.wL,  g_wL);

    cudaFuncSetAttribute(gemm_mma, cudaFuncAttributeMaxDynamicSharedMemorySize, SMEM_TOT);

    // layer 1 laid out explicitly so the 4th launch (ncu capture slot) = gemm_mma
    prep128<<<576 + 2560, 256>>>(B.colH, B.colL);                           // 1: tab128 + L1 pad rows
    convW<<<(64 * 32 + 255) / 256, 256>>>(w11, B.wH, B.wL, 64, 27, 32);     // 2
    im2col2<<<dim3(131072 / 256, 9), 256>>>(x, B.colH, B.colL, 3, 16384, 131072, TB128); // 3
    {
        dim3 gg(131072 / 128, 1, 1);
        gemm_mma<<<gg, 256, SMEM_TOT>>>(B.colH, B.colL, B.wH, B.wL, B.bufA, B.part,
                                        131072, 32, 32, 64, 16384);         // 4 <- profiled
    }
    conv_tc(B, B.bufA, B.bufB, w12, 64, 64, 128, TB128, 1);
    build_tab<<<(64*64*9 + 255) / 256, 256>>>(64, TB64);
    build_tab<<<(32*32*9 + 255) / 256, 256>>>(32, TB32);
    build_tab<<<(16*16*9 + 255) / 256, 256>>>(16, TB16);
    build_tab<<<(8*8*9 + 255) / 256, 256>>>(8, TB8);
    maxpool2<<<(BATCH*64*64*64 + 255) / 256, 256>>>(B.bufB, B.bufA, 64, 128);

    conv_tc(B, B.bufA, B.bufB, w21, 64, 128, 64, TB64, 1);
    conv_tc(B, B.bufB, B.bufA, w22, 128, 128, 64, TB64, 1);
    maxpool2<<<(BATCH*128*32*32 + 255) / 256, 256>>>(B.bufA, B.bufB, 128, 64);

    conv_tc(B, B.bufB, B.bufA, w31, 128, 256, 32, TB32, 1);
    conv_tc(B, B.bufA, B.bufB, w32, 256, 256, 32, TB32, 1);
    conv_tc(B, B.bufB, B.bufA, w33, 256, 256, 32, TB32, 1);
    maxpool2<<<(BATCH*256*16*16 + 255) / 256, 256>>>(B.bufA, B.bufB, 256, 32);

    conv_tc(B, B.bufB, B.bufA, w41, 256, 512, 16, TB16, 1);
    conv_tc(B, B.bufA, B.bufB, w42, 512, 512, 16, TB16, 1);
    conv_tc(B, B.bufB, B.bufA, w43, 512, 512, 16, TB16, 1);
    maxpool2<<<(BATCH*512*8*8 + 255) / 256, 256>>>(B.bufA, B.bufB, 512, 16);

    conv_tc(B, B.bufB, B.bufA, w51, 512, 512, 8, TB8, 4);
    conv_tc(B, B.bufA, B.bufB, w52, 512, 512, 8, TB8, 4);
    conv_tc(B, B.bufB, B.bufA, w53, 512, 512, 8, TB8, 4);
    maxpool2<<<(BATCH*512*4*4 + 255) / 256, 256>>>(B.bufA, B.bufB, 512, 8);

    avgpool4<<<(BATCH*512 + 255) / 256, 256>>>(B.bufB, B.vec1);
    fc_kernel<<<(4096*32 + 255) / 256, 256>>>(B.vec1, fc1w, fc1b, B.vec2, 512, 4096, 1);
    fc_kernel<<<(4096*32 + 255) / 256, 256>>>(B.vec2, fc2w, fc2b, B.vec1, 4096, 4096, 1);
    fc_kernel<<<(30*32 + 255) / 256, 256>>>(B.vec1, fc3w, fc3b, outp, 4096, 30, 0);
}

// round 7
// speedup vs baseline: 2.9272x; 1.0265x over previous
#include <cuda_runtime.h>
#include <cuda_bf16.h>
#include <cstdint>

#define BATCH 8

// ---------------- scratch ----------------
__device__ float g_bufA[8u*64u*128u*128u];
__device__ float g_bufB[8u*64u*128u*128u];
__device__ __nv_bfloat16 g_colH[75497472u];   // [k][n] hi plane
__device__ __nv_bfloat16 g_colL[75497472u];   // lo plane
__device__ __nv_bfloat16 g_wH[2359296u];
__device__ __nv_bfloat16 g_wL[2359296u];
__device__ float g_part[4194304u];            // up to 8 split-K slabs
__device__ int4   g_tabI[196416];
__device__ float4 g_tabW[196416];
__device__ float g_vec1[8*4096];
__device__ float g_vec2[8*4096];

#define TB128 0
#define TB64  147456
#define TB32  184320
#define TB16  193536
#define TB8   195840

// ---------------- PTX helpers (family-common sm_80+) ----------------
__device__ __forceinline__ uint32_t s2u(const void* p) {
    uint32_t a;
    asm("{ .reg .u64 t; cvta.to.shared.u64 t, %1; cvt.u32.u64 %0, t; }" : "=r"(a) : "l"(p));
    return a;
}
#define CPA(dst, src) asm volatile("cp.async.cg.shared.global [%0], [%1], 16;" :: "r"(dst), "l"(src))
#define CPA_COMMIT()  asm volatile("cp.async.commit_group;" ::: "memory")
#define CPA_WAIT0()   asm volatile("cp.async.wait_group 0;" ::: "memory")
#define LDM4(r, addr) asm volatile("ldmatrix.sync.aligned.m8n8.x4.shared.b16 {%0,%1,%2,%3}, [%4];" \
    : "=r"((r)[0]), "=r"((r)[1]), "=r"((r)[2]), "=r"((r)[3]) : "r"(addr))
#define LDM4T(r, addr) asm volatile("ldmatrix.sync.aligned.m8n8.x4.trans.shared.b16 {%0,%1,%2,%3}, [%4];" \
    : "=r"((r)[0]), "=r"((r)[1]), "=r"((r)[2]), "=r"((r)[3]) : "r"(addr))
#define MMA(d, a, b) asm volatile( \
    "mma.sync.aligned.m16n8k16.row.col.f32.bf16.bf16.f32 {%0,%1,%2,%3},{%4,%5,%6,%7},{%8,%9},{%0,%1,%2,%3};" \
    : "+f"((d)[0]), "+f"((d)[1]), "+f"((d)[2]), "+f"((d)[3]) \
    : "r"((a)[0]), "r"((a)[1]), "r"((a)[2]), "r"((a)[3]), "r"((b)[0]), "r"((b)[1]))

// ---------------- tab build ----------------
__device__ __forceinline__ void tab_one(int t, int H, int base) {
    int HW = H * H;
    if (t >= HW * 9) return;
    int k = t % 9, pos = t / 9;
    int y = pos / H, x = pos % H;

    float cc = 0.5f * (float)H - 0.5f;
    float th = atan2f((float)x - cc, (float)y - cc);
    if (th < 0.f) th += 6.28318530717958647692f;
    th = rintf(th * 10000.0f) / 10000.0f;

    int ky = k / 3, kx = k % 3;
    float offy = 0.f, offx = 0.f;
    if (k != 4) {
        int m = (k < 4) ? k : k - 1;
        float ang = th + (float)(3.14159265358979323846 * 0.25 * (double)m);
        offy = cosf(ang) + (float)(1 - ky);
        offx = sinf(ang) + (float)(1 - kx);
    }
    float py = (float)(y - 1 + ky) + offy;
    float px = (float)(x - 1 + kx) + offx;
    float y0 = floorf(py), x0 = floorf(px);
    float fy = py - y0, fx = px - x0;
    float Hm = (float)(H - 1);

    float ys[2] = {y0, y0 + 1.f};
    float xs[2] = {x0, x0 + 1.f};
    float wy[2] = {1.f - fy, fy};
    float wx[2] = {1.f - fx, fx};

    int ids[4]; float ws[4]; int q = 0;
    #pragma unroll
    for (int iy = 0; iy < 2; iy++) {
        #pragma unroll
        for (int ix = 0; ix < 2; ix++) {
            float yf = ys[iy], xf = xs[ix];
            bool v = (yf >= 0.f) && (yf <= Hm) && (xf >= 0.f) && (xf <= Hm);
            int yi = (int)fminf(fmaxf(yf, 0.f), Hm);
            int xi = (int)fminf(fmaxf(xf, 0.f), Hm);
            ids[q] = yi * H + xi;
            ws[q]  = v ? (wy[iy] * wx[ix]) : 0.f;
            q++;
        }
    }
    g_tabI[base + t] = make_int4(ids[0], ids[1], ids[2], ids[3]);
    g_tabW[base + t] = make_float4(ws[0], ws[1], ws[2], ws[3]);
}

__global__ void build_tab(int H, int base) {
    tab_one(blockIdx.x * blockDim.x + threadIdx.x, H, base);
}

__global__ void prep128(__nv_bfloat16* colH, __nv_bfloat16* colL) {
    if (blockIdx.x < 576) {
        tab_one(blockIdx.x * 256 + threadIdx.x, 128, TB128);
    } else {
        int i = (blockIdx.x - 576) * 256 + threadIdx.x;
        if (i < 5 * 131072) {
            size_t off = (size_t)27 * 131072 + i;
            colH[off] = __float2bfloat16(0.f);
            colL[off] = __float2bfloat16(0.f);
        }
    }
}

// ---------------- deformable im2col -> bf16 hi/lo, [k][n] ----------------
__global__ void im2col2(const float* __restrict__ x, __nv_bfloat16* __restrict__ colH,
                        __nv_bfloat16* __restrict__ colL, int Cin, int HW, int Ntot,
                        int tabBase) {
    int n = blockIdx.x * blockDim.x + threadIdx.x;
    int tap = blockIdx.y;
    int pos = n % HW, b = n / HW;
    int4   id = g_tabI[tabBase + pos * 9 + tap];
    float4 w  = g_tabW[tabBase + pos * 9 + tap];
    const float* xb = x + (size_t)b * Cin * HW;
    size_t cstep = (size_t)9 * Ntot;
    __nv_bfloat16* pH = colH + (size_t)tap * Ntot + n;
    __nv_bfloat16* pL = colL + (size_t)tap * Ntot + n;
    for (int c = 0; c < Cin; c++) {
        const float* xc = xb + (size_t)c * HW;
        float v = xc[id.x] * w.x + xc[id.y] * w.y + xc[id.z] * w.z + xc[id.w] * w.w;
        __nv_bfloat16 h = __float2bfloat16(v);
        pH[c * cstep] = h;
        pL[c * cstep] = __float2bfloat16(v - __bfloat162float(h));
    }
}

// ---------------- weight fp32 -> bf16 hi/lo, padded to Kpad ----------------
__global__ void convW(const float* __restrict__ W, __nv_bfloat16* __restrict__ wH,
                      __nv_bfloat16* __restrict__ wL, int O, int Kreal, int Kpad) {
    int t = blockIdx.x * blockDim.x + threadIdx.x;
    if (t >= O * Kpad) return;
    int o = t / Kpad, k = t % Kpad;
    float w = (k < Kreal) ? W[(size_t)o * Kreal + k] : 0.f;
    __nv_bfloat16 h = __float2bfloat16(w);
    wH[t] = h;
    wL[t] = __float2bfloat16(w - __bfloat162float(h));
}

// ---------------- HMMA GEMM 256x64x32, warp tile 64x32 ----------------
// stage bytes: AH@0 (32 k-rows x 264 el), AL@16896, BH@33792 (64 x 40 el), BL@38912; stage 44032
#define RSA 264
#define RSB 40
#define OF_AL 16896
#define OF_B  33792
#define OF_BL 5120
#define STAGE_B 44032
#define SMEM_TOT 88064
__global__ void __launch_bounds__(256) gemm_mma(
    const __nv_bfloat16* __restrict__ AH, const __nv_bfloat16* __restrict__ AL,
    const __nv_bfloat16* __restrict__ WH, const __nv_bfloat16* __restrict__ WL,
    float* __restrict__ out, float* __restrict__ part,
    int Ntot, int Kpad, int chunkK, int Cout, int HW) {
    extern __shared__ char smem[];
    uint32_t sb0 = s2u(smem);
    int tid = threadIdx.x, l = tid & 31, wid = tid >> 5;
    int wm = wid & 3, wn = wid >> 2;                 // 4 m-warps x 2 n-warps
    int bn = blockIdx.x * 256, bo = blockIdx.y * 64;
    int kStart = blockIdx.z * chunkK;
    int nk = chunkK >> 5;

    float acc[4][4][4];
    #pragma unroll
    for (int i = 0; i < 4; i++)
        #pragma unroll
        for (int j = 0; j < 4; j++)
            #pragma unroll
            for (int q = 0; q < 4; q++) acc[i][j][q] = 0.f;

    auto load_stage = [&](int st, int k0) {
        uint32_t sb = sb0 + st * STAGE_B;
        // A: 2 planes x 32 k-rows x 32 chunks(16B) = 2048
        #pragma unroll
        for (int i = 0; i < 8; i++) {
            int u = tid + i * 256;
            int plane = u >> 10, rem = u & 1023;
            int krow = rem >> 5, c = rem & 31;
            const __nv_bfloat16* src = (plane ? AL : AH) + (size_t)(k0 + krow) * Ntot + bn + c * 8;
            uint32_t dst = sb + plane * OF_AL + (uint32_t)(krow * RSA + c * 8) * 2;
            CPA(dst, src);
        }
        // B: 2 planes x 64 rows x 4 chunks = 512
        #pragma unroll
        for (int i = 0; i < 2; i++) {
            int u = tid + i * 256;
            int plane = u >> 8, rem = u & 255;
            int row = rem >> 2, c = rem & 3;
            const __nv_bfloat16* src = (plane ? WL : WH) + (size_t)(bo + row) * Kpad + k0 + c * 8;
            uint32_t dst = sb + OF_B + plane * OF_BL + (uint32_t)(row * RSB + c * 8) * 2;
            CPA(dst, src);
        }
        CPA_COMMIT();
    };

    load_stage(0, kStart);

    int krow = (l & 7) + ((l & 16) >> 1);
    int mcol = (l & 8);
    int browA = (l & 7) + ((l >> 4) << 3);
    int bcol  = ((l >> 3) & 1) * 8;

    for (int it = 0; it < nk; it++) {
        CPA_WAIT0();
        __syncthreads();
        if (it + 1 < nk) load_stage((it + 1) & 1, kStart + (it + 1) * 32);

        uint32_t base = sb0 + (it & 1) * STAGE_B;
        #pragma unroll
        for (int ks = 0; ks < 2; ks++) {
            uint32_t aH[4][4], aL[4][4], bH[4][2], bL[4][2];
            #pragma unroll
            for (int mi = 0; mi < 4; mi++) {
                uint32_t off = (uint32_t)((ks * 16 + krow) * RSA + wm * 64 + mi * 16 + mcol) * 2;
                LDM4T(aH[mi], base + off);
                LDM4T(aL[mi], base + OF_AL + off);
            }
            #pragma unroll
            for (int j = 0; j < 2; j++) {
                int row = wn * 32 + j * 16 + browA;
                uint32_t off = OF_B + (uint32_t)(row * RSB + ks * 16 + bcol) * 2;
                uint32_t r[4];
                LDM4(r, base + off);
                bH[2*j][0] = r[0]; bH[2*j][1] = r[1]; bH[2*j+1][0] = r[2]; bH[2*j+1][1] = r[3];
                LDM4(r, base + off + OF_BL);
                bL[2*j][0] = r[0]; bL[2*j][1] = r[1]; bL[2*j+1][0] = r[2]; bL[2*j+1][1] = r[3];
            }
            #pragma unroll
            for (int mi = 0; mi < 4; mi++)
                #pragma unroll
                for (int nf = 0; nf < 4; nf++) {
                    MMA(acc[mi][nf], aH[mi], bH[nf]);
                    MMA(acc[mi][nf], aH[mi], bL[nf]);
                    MMA(acc[mi][nf], aL[mi], bH[nf]);
                }
        }
        __syncthreads();
    }

    bool dosplit = (gridDim.z > 1);
    #pragma unroll
    for (int mi = 0; mi < 4; mi++)
        #pragma unroll
        for (int nf = 0; nf < 4; nf++) {
            int row0 = bn + wm * 64 + mi * 16 + (l >> 2);
            int col0 = bo + wn * 32 + nf * 8 + 2 * (l & 3);
            float* d = acc[mi][nf];
            if (dosplit) {
                size_t zb = (size_t)blockIdx.z * Cout;
                part[(zb + col0)     * Ntot + row0]     = d[0];
                part[(zb + col0 + 1) * Ntot + row0]     = d[1];
                part[(zb + col0)     * Ntot + row0 + 8] = d[2];
                part[(zb + col0 + 1) * Ntot + row0 + 8] = d[3];
            } else {
                int b0 = row0 / HW, p0 = row0 % HW;
                int r1 = row0 + 8;
                int b1 = r1 / HW, p1 = r1 % HW;
                out[((size_t)b0 * Cout + col0)     * HW + p0] = fmaxf(d[0], 0.f);
                out[((size_t)b0 * Cout + col0 + 1) * HW + p0] = fmaxf(d[1], 0.f);
                out[((size_t)b1 * Cout + col0)     * HW + p1] = fmaxf(d[2], 0.f);
                out[((size_t)b1 * Cout + col0 + 1) * HW + p1] = fmaxf(d[3], 0.f);
            }
        }
}

// ---------------- split-K reduce + ReLU ----------------
__global__ void reduceK(const float* __restrict__ part, float* __restrict__ out,
                        int Cout, int N, int HW, int nslab) {
    int t = blockIdx.x * blockDim.x + threadIdx.x;
    if (t >= Cout * N) return;
    int o = t / N, n = t % N;
    float s = 0.f;
    for (int z = 0; z < nslab; z++)
        s += part[((size_t)z * Cout + o) * N + n];
    int b = n / HW, pos = n % HW;
    out[((size_t)b * Cout + o) * HW + pos] = fmaxf(s, 0.f);
}

// ---------------- pools / FC ----------------
__global__ void maxpool2(const float* __restrict__ in, float* __restrict__ out, int C, int H) {
    int Ho = H >> 1;
    int total = BATCH * C * Ho * Ho;
    int t = blockIdx.x * blockDim.x + threadIdx.x;
    if (t >= total) return;
    int xo = t % Ho;
    int tmp = t / Ho;
    int yo = tmp % Ho;
    int bc = tmp / Ho;
    const float* p = in + ((size_t)bc * H + 2 * yo) * H + 2 * xo;
    out[t] = fmaxf(fmaxf(p[0], p[1]), fmaxf(p[H], p[H + 1]));
}

__global__ void avgpool4(const float* __restrict__ in, float* __restrict__ out) {
    int t = blockIdx.x * blockDim.x + threadIdx.x;
    if (t >= BATCH * 512) return;
    const float* p = in + (size_t)t * 16;
    float s = 0.f;
    #pragma unroll
    for (int i = 0; i < 16; i++) s += p[i];
    out[t] = s * (1.f / 16.f);
}

__global__ void fc_kernel(const float* __restrict__ v, const float* __restrict__ Wf,
                          const float* __restrict__ bias, float* __restrict__ out,
                          int In, int Out, int doRelu) {
    int warp = (blockIdx.x * blockDim.x + threadIdx.x) >> 5;
    int lane = threadIdx.x & 31;
    if (warp >= Out) return;
    const float* wrow = Wf + (size_t)warp * In;
    float acc[BATCH];
    #pragma unroll
    for (int b = 0; b < BATCH; b++) acc[b] = 0.f;
    for (int i = lane; i < In; i += 32) {
        float wv = wrow[i];
        #pragma unroll
        for (int b = 0; b < BATCH; b++)
            acc[b] = fmaf(wv, v[b * In + i], acc[b]);
    }
    #pragma unroll
    for (int b = 0; b < BATCH; b++) {
        #pragma unroll
        for (int off = 16; off; off >>= 1)
            acc[b] += __shfl_xor_sync(0xffffffffu, acc[b], off);
    }
    if (lane == 0) {
        float bi = bias[warp];
        #pragma unroll
        for (int b = 0; b < BATCH; b++) {
            float r = acc[b] + bi;
            if (doRelu) r = fmaxf(r, 0.f);
            out[b * Out + warp] = r;
        }
    }
}

// ---------------- host ----------------
struct Bufs {
    float *bufA, *bufB, *part, *vec1, *vec2;
    __nv_bfloat16 *colH, *colL, *wH, *wL;
};

static void conv_tc(const Bufs& B, const float* in, float* out, const float* wt,
                    int Cin, int Cout, int H, int tabBase, int nsplit) {
    int HW = H * H;
    int Ntot = BATCH * HW;
    int Kreal = Cin * 9;
    int Kpad = (Kreal + 31) & ~31;
    im2col2<<<dim3(Ntot / 256, 9), 256>>>(in, B.colH, B.colL, Cin, HW, Ntot, tabBase);
    convW<<<(Cout * Kpad + 255) / 256, 256>>>(wt, B.wH, B.wL, Cout, Kreal, Kpad);
    dim3 gg(Ntot / 256, Cout / 64, nsplit);
    gemm_mma<<<gg, 256, SMEM_TOT>>>(B.colH, B.colL, B.wH, B.wL, out, B.part,
                                    Ntot, Kpad, Kpad / nsplit, Cout, HW);
    if (nsplit > 1)
        reduceK<<<(Cout * Ntot + 255) / 256, 256>>>(B.part, out, Cout, Ntot, HW, nsplit);
}

extern "C" void kernel_launch(void* const* d_in, const int* in_sizes, int n_in,
                              void* d_out, int out_size) {
    const float* x   = (const float*)d_in[0];
    const float* w11 = (const float*)d_in[1];
    const float* w12 = (const float*)d_in[2];
    const float* w21 = (const float*)d_in[3];
    const float* w22 = (const float*)d_in[4];
    const float* w31 = (const float*)d_in[5];
    const float* w32 = (const float*)d_in[6];
    const float* w33 = (const float*)d_in[7];
    const float* w41 = (const float*)d_in[8];
    const float* w42 = (const float*)d_in[9];
    const float* w43 = (const float*)d_in[10];
    const float* w51 = (const float*)d_in[11];
    const float* w52 = (const float*)d_in[12];
    const float* w53 = (const float*)d_in[13];
    const float* fc1w = (const float*)d_in[14];
    const float* fc1b = (const float*)d_in[15];
    const float* fc2w = (const float*)d_in[16];
    const float* fc2b = (const float*)d_in[17];
    const float* fc3w = (const float*)d_in[18];
    const float* fc3b = (const float*)d_in[19];
    float* outp = (float*)d_out;

    Bufs B;
    cudaGetSymbolAddress((void**)&B.bufA, g_bufA);
    cudaGetSymbolAddress((void**)&B.bufB, g_bufB);
    cudaGetSymbolAddress((void**)&B.part, g_part);
    cudaGetSymbolAddress((void**)&B.vec1, g_vec1);
    cudaGetSymbolAddress((void**)&B.vec2, g_vec2);
    cudaGetSymbolAddress((void**)&B.colH, g_colH);
    cudaGetSymbolAddress((void**)&B.colL, g_colL);
    cudaGetSymbolAddress((void**)&B.wH,  g_wH);
    cudaGetSymbolAddress((void**)&B.wL,  g_wL);

    cudaFuncSetAttribute(gemm_mma, cudaFuncAttributeMaxDynamicSharedMemorySize, SMEM_TOT);

    prep128<<<576 + 2560, 256>>>(B.colH, B.colL);                           // 1
    convW<<<(64 * 32 + 255) / 256, 256>>>(w11, B.wH, B.wL, 64, 27, 32);     // 2
    im2col2<<<dim3(131072 / 256, 9), 256>>>(x, B.colH, B.colL, 3, 16384, 131072, TB128); // 3
    {
        dim3 gg(131072 / 256, 1, 1);
        gemm_mma<<<gg, 256, SMEM_TOT>>>(B.colH, B.colL, B.wH, B.wL, B.bufA, B.part,
                                        131072, 32, 32, 64, 16384);         // 4 (profiled)
    }
    conv_tc(B, B.bufA, B.bufB, w12, 64, 64, 128, TB128, 1);
    build_tab<<<(64*64*9 + 255) / 256, 256>>>(64, TB64);
    build_tab<<<(32*32*9 + 255) / 256, 256>>>(32, TB32);
    build_tab<<<(16*16*9 + 255) / 256, 256>>>(16, TB16);
    build_tab<<<(8*8*9 + 255) / 256, 256>>>(8, TB8);
    maxpool2<<<(BATCH*64*64*64 + 255) / 256, 256>>>(B.bufB, B.bufA, 64, 128);

    conv_tc(B, B.bufA, B.bufB, w21, 64, 128, 64, TB64, 1);
    conv_tc(B, B.bufB, B.bufA, w22, 128, 128, 64, TB64, 1);
    maxpool2<<<(BATCH*128*32*32 + 255) / 256, 256>>>(B.bufA, B.bufB, 128, 64);

    conv_tc(B, B.bufB, B.bufA, w31, 128, 256, 32, TB32, 1);
    conv_tc(B, B.bufA, B.bufB, w32, 256, 256, 32, TB32, 1);
    conv_tc(B, B.bufB, B.bufA, w33, 256, 256, 32, TB32, 1);
    maxpool2<<<(BATCH*256*16*16 + 255) / 256, 256>>>(B.bufA, B.bufB, 256, 32);

    conv_tc(B, B.bufB, B.bufA, w41, 256, 512, 16, TB16, 2);
    conv_tc(B, B.bufA, B.bufB, w42, 512, 512, 16, TB16, 2);
    conv_tc(B, B.bufB, B.bufA, w43, 512, 512, 16, TB16, 2);
    maxpool2<<<(BATCH*512*8*8 + 255) / 256, 256>>>(B.bufA, B.bufB, 512, 16);

    conv_tc(B, B.bufB, B.bufA, w51, 512, 512, 8, TB8, 8);
    conv_tc(B, B.bufA, B.bufB, w52, 512, 512, 8, TB8, 8);
    conv_tc(B, B.bufB, B.bufA, w53, 512, 512, 8, TB8, 8);
    maxpool2<<<(BATCH*512*4*4 + 255) / 256, 256>>>(B.bufA, B.bufB, 512, 8);

    avgpool4<<<(BATCH*512 + 255) / 256, 256>>>(B.bufB, B.vec1);
    fc_kernel<<<(4096*32 + 255) / 256, 256>>>(B.vec1, fc1w, fc1b, B.vec2, 512, 4096, 1);
    fc_kernel<<<(4096*32 + 255) / 256, 256>>>(B.vec2, fc2w, fc2b, B.vec1, 4096, 4096, 1);
    fc_kernel<<<(30*32 + 255) / 256, 256>>>(B.vec1, fc3w, fc3b, outp, 4096, 30, 0);
}